// round 14
// baseline (speedup 1.0000x reference)
#include <cuda_runtime.h>
#include <cuda_bf16.h>
#include <math_constants.h>
#include <cstdint>

// Problem shape (fixed by the reference)
#define L_DIM 1024
#define B_DIM 64
#define H_DIM 1024

#define SPLITS 4                        // grid (4, 64) = 256 CTAs, occ 2
#define WARPS_PER_BLOCK 8
#define ROWS_PER_SPLIT (L_DIM / SPLITS) // 256
#define HV 8                            // float4 vectors per thread (H/128)
#define PF_ITERS 4                      // prefetch distance in warp-iterations
#define PF_ROWS (PF_ITERS * WARPS_PER_BLOCK)

// Scratch: per-(b,split) context vector + (M, D). 1 MB total.
__device__ float g_ctx[B_DIM * SPLITS * H_DIM];
__device__ float g_m[B_DIM * SPLITS];
__device__ float g_d[B_DIM * SPLITS];
__device__ int   g_cnt[B_DIM];          // zero-initialized; reset by last CTA each run

__device__ __forceinline__ void prefetch_l2(const void* p) {
    asm volatile("prefetch.global.L2 [%0];" :: "l"(p));
}

// ---------------------------------------------------------------------------
// R13 structure, prefetch distance 2 -> 4 iterations.
// grid: (SPLITS, B) = 256 CTAs, block 256 (8 warps), occ 2.
// ---------------------------------------------------------------------------
__global__ __launch_bounds__(256, 2)
void attn_fused(const float* __restrict__ enc,   // [L, B, H]
                const float* __restrict__ dec,   // [1, B, H]
                float* __restrict__ out)         // [B, H]
{
    const int s    = blockIdx.x;
    const int b    = blockIdx.y;
    const int warp = threadIdx.x >> 5;
    const int lane = threadIdx.x & 31;

    __shared__ float s_acc[WARPS_PER_BLOCK][H_DIM];   // 32 KB
    __shared__ float s_m[WARPS_PER_BLOCK];
    __shared__ float s_d[WARPS_PER_BLOCK];
    __shared__ float s_scale[WARPS_PER_BLOCK];
    __shared__ int   s_is_last;

    // Decoder slice in registers: h = k*128 + lane*4
    const float4* dec4 = reinterpret_cast<const float4*>(dec + (size_t)b * H_DIM);
    float4 dv[HV];
#pragma unroll
    for (int k = 0; k < HV; k++) dv[k] = dec4[k * 32 + lane];

    float4 acc[HV];
#pragma unroll
    for (int k = 0; k < HV; k++) acc[k] = make_float4(0.f, 0.f, 0.f, 0.f);
    float m = -CUDART_INF_F;
    float d = 0.f;

    const int l0 = s * ROWS_PER_SPLIT + warp;
    const int l1 = (s + 1) * ROWS_PER_SPLIT;

    // Warm the prefetch pipeline: the first PF_ITERS iterations' rows.
#pragma unroll
    for (int i = 0; i < PF_ITERS; i++) {
        const int lw = min(l0 + i * WARPS_PER_BLOCK, l1 - 1);
        const char* pw = reinterpret_cast<const char*>(
            enc + ((size_t)lw * B_DIM + b) * H_DIM);
        prefetch_l2(pw + lane * 128);
    }

    for (int l = l0; l < l1; l += WARPS_PER_BLOCK) {
        // ---- prefetch the row PF_ITERS iterations ahead (1 inst, 0 regs) ----
        {
            const int lp = min(l + PF_ROWS, l1 - 1);   // clamp: stay in-bounds
            const char* pp = reinterpret_cast<const char*>(
                enc + ((size_t)lp * B_DIM + b) * H_DIM);
            prefetch_l2(pp + lane * 128);              // 32 lanes cover 4 KB row
        }

        const float4* e4 =
            reinterpret_cast<const float4*>(enc + ((size_t)l * B_DIM + b) * H_DIM);
        float4 ev[HV];
#pragma unroll
        for (int k = 0; k < HV; k++) ev[k] = __ldcs(&e4[k * 32 + lane]);  // L2-hot

        // dot(e, dec): per-thread partial, warp butterfly reduce
        float sc = 0.f;
#pragma unroll
        for (int k = 0; k < HV; k++) {
            sc = fmaf(ev[k].x, dv[k].x, sc);
            sc = fmaf(ev[k].y, dv[k].y, sc);
            sc = fmaf(ev[k].z, dv[k].z, sc);
            sc = fmaf(ev[k].w, dv[k].w, sc);
        }
#pragma unroll
        for (int off = 16; off > 0; off >>= 1)
            sc += __shfl_xor_sync(0xffffffffu, sc, off);

        // branch-free online softmax update (R3 form)
        float nm    = fmaxf(m, sc);
        float alpha = __expf(m - nm);     // 0 on first iter (m = -inf)
        float w     = __expf(sc - nm);
        d = d * alpha + w;
        m = nm;
#pragma unroll
        for (int k = 0; k < HV; k++) {
            acc[k].x = fmaf(w, ev[k].x, acc[k].x * alpha);
            acc[k].y = fmaf(w, ev[k].y, acc[k].y * alpha);
            acc[k].z = fmaf(w, ev[k].z, acc[k].z * alpha);
            acc[k].w = fmaf(w, ev[k].w, acc[k].w * alpha);
        }
    }

    // ---- in-block flash combine of the 8 warp partials ----
#pragma unroll
    for (int k = 0; k < HV; k++)
        *reinterpret_cast<float4*>(&s_acc[warp][k * 128 + lane * 4]) = acc[k];
    if (lane == 0) { s_m[warp] = m; s_d[warp] = d; }
    __syncthreads();

    if (threadIdx.x == 0) {
        float M = -CUDART_INF_F;
#pragma unroll
        for (int w = 0; w < WARPS_PER_BLOCK; w++) M = fmaxf(M, s_m[w]);
        float D = 0.f;
#pragma unroll
        for (int w = 0; w < WARPS_PER_BLOCK; w++) {
            float sc = __expf(s_m[w] - M);
            s_scale[w] = sc;
            D += s_d[w] * sc;
        }
        const int pid = b * SPLITS + s;
        g_m[pid] = M;
        g_d[pid] = D;
    }
    __syncthreads();

    // Each thread reduces 4 h-positions across the 8 warp slots (float4).
    {
        const int h = threadIdx.x * 4;
        float4 sum = make_float4(0.f, 0.f, 0.f, 0.f);
#pragma unroll
        for (int w = 0; w < WARPS_PER_BLOCK; w++) {
            float sc = s_scale[w];
            float4 v = *reinterpret_cast<const float4*>(&s_acc[w][h]);
            sum.x = fmaf(sc, v.x, sum.x);
            sum.y = fmaf(sc, v.y, sum.y);
            sum.z = fmaf(sc, v.z, sum.z);
            sum.w = fmaf(sc, v.w, sum.w);
        }
        const int pid = b * SPLITS + s;
        *reinterpret_cast<float4*>(&g_ctx[(size_t)pid * H_DIM + h]) = sum;
    }

    // ---- last-CTA-per-b cross-split combine ----
    __threadfence();
    if (threadIdx.x == 0)
        s_is_last = (atomicAdd(&g_cnt[b], 1) == SPLITS - 1) ? 1 : 0;
    __syncthreads();
    if (!s_is_last) return;

    __threadfence();   // acquire: order reads of peers' partials after the atomic

    float M = -CUDART_INF_F;
#pragma unroll
    for (int p = 0; p < SPLITS; p++) M = fmaxf(M, g_m[b * SPLITS + p]);
    float D = 0.f;
    float scale[SPLITS];
#pragma unroll
    for (int p = 0; p < SPLITS; p++) {
        scale[p] = __expf(g_m[b * SPLITS + p] - M);
        D += g_d[b * SPLITS + p] * scale[p];
    }
    const float invD = 1.f / D;

    {
        const int h = threadIdx.x * 4;
        float4 sum = make_float4(0.f, 0.f, 0.f, 0.f);
#pragma unroll
        for (int p = 0; p < SPLITS; p++) {
            const float sc = scale[p] * invD;
            float4 v = *reinterpret_cast<const float4*>(
                &g_ctx[((size_t)(b * SPLITS + p)) * H_DIM + h]);
            sum.x = fmaf(sc, v.x, sum.x);
            sum.y = fmaf(sc, v.y, sum.y);
            sum.z = fmaf(sc, v.z, sum.z);
            sum.w = fmaf(sc, v.w, sum.w);
        }
        *reinterpret_cast<float4*>(&out[(size_t)b * H_DIM + h]) = sum;
    }

    if (threadIdx.x == 0) g_cnt[b] = 0;   // reset for next graph replay
}

// ---------------------------------------------------------------------------
extern "C" void kernel_launch(void* const* d_in, const int* in_sizes, int n_in,
                              void* d_out, int out_size)
{
    const float* enc = (const float*)d_in[0];   // [1024, 64, 1024]
    const float* dec = (const float*)d_in[1];   // [1, 64, 1024]
    float* out = (float*)d_out;                 // [64, 1024]

    dim3 grid(SPLITS, B_DIM);
    attn_fused<<<grid, 256>>>(enc, dec, out);
}

// round 15
// speedup vs baseline: 1.0356x; 1.0356x over previous
#include <cuda_runtime.h>
#include <cuda_bf16.h>
#include <math_constants.h>
#include <cstdint>

// Problem shape (fixed by the reference)
#define L_DIM 1024
#define B_DIM 64
#define H_DIM 1024

#define SPLITS 4                        // grid (4, 64) = 256 CTAs, occ 2
#define WARPS_PER_BLOCK 8
#define ROWS_PER_SPLIT (L_DIM / SPLITS) // 256
#define HV 8                            // float4 vectors per thread (H/128)
#define PF_ITERS 3                      // prefetch distance in warp-iterations
#define PF_ROWS (PF_ITERS * WARPS_PER_BLOCK)

// Scratch: per-(b,split) context vector + (M, D). 1 MB total.
__device__ float g_ctx[B_DIM * SPLITS * H_DIM];
__device__ float g_m[B_DIM * SPLITS];
__device__ float g_d[B_DIM * SPLITS];
__device__ int   g_cnt[B_DIM];          // zero-initialized; reset by last CTA each run

__device__ __forceinline__ void prefetch_l2(const void* p) {
    asm volatile("prefetch.global.L2 [%0];" :: "l"(p));
}

// ---------------------------------------------------------------------------
// R13 structure, prefetch distance 3 iterations (single-variable tune).
// grid: (SPLITS, B) = 256 CTAs, block 256 (8 warps), occ 2.
// ---------------------------------------------------------------------------
__global__ __launch_bounds__(256, 2)
void attn_fused(const float* __restrict__ enc,   // [L, B, H]
                const float* __restrict__ dec,   // [1, B, H]
                float* __restrict__ out)         // [B, H]
{
    const int s    = blockIdx.x;
    const int b    = blockIdx.y;
    const int warp = threadIdx.x >> 5;
    const int lane = threadIdx.x & 31;

    __shared__ float s_acc[WARPS_PER_BLOCK][H_DIM];   // 32 KB
    __shared__ float s_m[WARPS_PER_BLOCK];
    __shared__ float s_d[WARPS_PER_BLOCK];
    __shared__ float s_scale[WARPS_PER_BLOCK];
    __shared__ int   s_is_last;

    // Decoder slice in registers: h = k*128 + lane*4
    const float4* dec4 = reinterpret_cast<const float4*>(dec + (size_t)b * H_DIM);
    float4 dv[HV];
#pragma unroll
    for (int k = 0; k < HV; k++) dv[k] = dec4[k * 32 + lane];

    float4 acc[HV];
#pragma unroll
    for (int k = 0; k < HV; k++) acc[k] = make_float4(0.f, 0.f, 0.f, 0.f);
    float m = -CUDART_INF_F;
    float d = 0.f;

    const int l0 = s * ROWS_PER_SPLIT + warp;
    const int l1 = (s + 1) * ROWS_PER_SPLIT;

    // Warm the prefetch pipeline: the first PF_ITERS iterations' rows.
#pragma unroll
    for (int i = 0; i < PF_ITERS; i++) {
        const int lw = min(l0 + i * WARPS_PER_BLOCK, l1 - 1);
        const char* pw = reinterpret_cast<const char*>(
            enc + ((size_t)lw * B_DIM + b) * H_DIM);
        prefetch_l2(pw + lane * 128);
    }

    for (int l = l0; l < l1; l += WARPS_PER_BLOCK) {
        // ---- prefetch the row PF_ITERS iterations ahead (1 inst, 0 regs) ----
        {
            const int lp = min(l + PF_ROWS, l1 - 1);   // clamp: stay in-bounds
            const char* pp = reinterpret_cast<const char*>(
                enc + ((size_t)lp * B_DIM + b) * H_DIM);
            prefetch_l2(pp + lane * 128);              // 32 lanes cover 4 KB row
        }

        const float4* e4 =
            reinterpret_cast<const float4*>(enc + ((size_t)l * B_DIM + b) * H_DIM);
        float4 ev[HV];
#pragma unroll
        for (int k = 0; k < HV; k++) ev[k] = __ldcs(&e4[k * 32 + lane]);  // L2-hot

        // dot(e, dec): per-thread partial, warp butterfly reduce
        float sc = 0.f;
#pragma unroll
        for (int k = 0; k < HV; k++) {
            sc = fmaf(ev[k].x, dv[k].x, sc);
            sc = fmaf(ev[k].y, dv[k].y, sc);
            sc = fmaf(ev[k].z, dv[k].z, sc);
            sc = fmaf(ev[k].w, dv[k].w, sc);
        }
#pragma unroll
        for (int off = 16; off > 0; off >>= 1)
            sc += __shfl_xor_sync(0xffffffffu, sc, off);

        // branch-free online softmax update (R3 form)
        float nm    = fmaxf(m, sc);
        float alpha = __expf(m - nm);     // 0 on first iter (m = -inf)
        float w     = __expf(sc - nm);
        d = d * alpha + w;
        m = nm;
#pragma unroll
        for (int k = 0; k < HV; k++) {
            acc[k].x = fmaf(w, ev[k].x, acc[k].x * alpha);
            acc[k].y = fmaf(w, ev[k].y, acc[k].y * alpha);
            acc[k].z = fmaf(w, ev[k].z, acc[k].z * alpha);
            acc[k].w = fmaf(w, ev[k].w, acc[k].w * alpha);
        }
    }

    // ---- in-block flash combine of the 8 warp partials ----
#pragma unroll
    for (int k = 0; k < HV; k++)
        *reinterpret_cast<float4*>(&s_acc[warp][k * 128 + lane * 4]) = acc[k];
    if (lane == 0) { s_m[warp] = m; s_d[warp] = d; }
    __syncthreads();

    if (threadIdx.x == 0) {
        float M = -CUDART_INF_F;
#pragma unroll
        for (int w = 0; w < WARPS_PER_BLOCK; w++) M = fmaxf(M, s_m[w]);
        float D = 0.f;
#pragma unroll
        for (int w = 0; w < WARPS_PER_BLOCK; w++) {
            float sc = __expf(s_m[w] - M);
            s_scale[w] = sc;
            D += s_d[w] * sc;
        }
        const int pid = b * SPLITS + s;
        g_m[pid] = M;
        g_d[pid] = D;
    }
    __syncthreads();

    // Each thread reduces 4 h-positions across the 8 warp slots (float4).
    {
        const int h = threadIdx.x * 4;
        float4 sum = make_float4(0.f, 0.f, 0.f, 0.f);
#pragma unroll
        for (int w = 0; w < WARPS_PER_BLOCK; w++) {
            float sc = s_scale[w];
            float4 v = *reinterpret_cast<const float4*>(&s_acc[w][h]);
            sum.x = fmaf(sc, v.x, sum.x);
            sum.y = fmaf(sc, v.y, sum.y);
            sum.z = fmaf(sc, v.z, sum.z);
            sum.w = fmaf(sc, v.w, sum.w);
        }
        const int pid = b * SPLITS + s;
        *reinterpret_cast<float4*>(&g_ctx[(size_t)pid * H_DIM + h]) = sum;
    }

    // ---- last-CTA-per-b cross-split combine ----
    __threadfence();
    if (threadIdx.x == 0)
        s_is_last = (atomicAdd(&g_cnt[b], 1) == SPLITS - 1) ? 1 : 0;
    __syncthreads();
    if (!s_is_last) return;

    __threadfence();   // acquire: order reads of peers' partials after the atomic

    float M = -CUDART_INF_F;
#pragma unroll
    for (int p = 0; p < SPLITS; p++) M = fmaxf(M, g_m[b * SPLITS + p]);
    float D = 0.f;
    float scale[SPLITS];
#pragma unroll
    for (int p = 0; p < SPLITS; p++) {
        scale[p] = __expf(g_m[b * SPLITS + p] - M);
        D += g_d[b * SPLITS + p] * scale[p];
    }
    const float invD = 1.f / D;

    {
        const int h = threadIdx.x * 4;
        float4 sum = make_float4(0.f, 0.f, 0.f, 0.f);
#pragma unroll
        for (int p = 0; p < SPLITS; p++) {
            const float sc = scale[p] * invD;
            float4 v = *reinterpret_cast<const float4*>(
                &g_ctx[((size_t)(b * SPLITS + p)) * H_DIM + h]);
            sum.x = fmaf(sc, v.x, sum.x);
            sum.y = fmaf(sc, v.y, sum.y);
            sum.z = fmaf(sc, v.z, sum.z);
            sum.w = fmaf(sc, v.w, sum.w);
        }
        *reinterpret_cast<float4*>(&out[(size_t)b * H_DIM + h]) = sum;
    }

    if (threadIdx.x == 0) g_cnt[b] = 0;   // reset for next graph replay
}

// ---------------------------------------------------------------------------
extern "C" void kernel_launch(void* const* d_in, const int* in_sizes, int n_in,
                              void* d_out, int out_size)
{
    const float* enc = (const float*)d_in[0];   // [1024, 64, 1024]
    const float* dec = (const float*)d_in[1];   // [1, 64, 1024]
    float* out = (float*)d_out;                 // [64, 1024]

    dim3 grid(SPLITS, B_DIM);
    attn_fused<<<grid, 256>>>(enc, dec, out);
}

// round 16
// speedup vs baseline: 1.1712x; 1.1310x over previous
#include <cuda_runtime.h>
#include <cuda_bf16.h>
#include <math_constants.h>
#include <cstdint>

// Problem shape (fixed by the reference)
#define L_DIM 1024
#define B_DIM 64
#define H_DIM 1024

#define SPLITS 4                        // grid (4, 64) = 256 CTAs, occ 2
#define WARPS_PER_BLOCK 8
#define ROWS_PER_SPLIT (L_DIM / SPLITS) // 256
#define HV 8                            // float4 vectors per thread (H/128)
#define PF_ITERS 1                      // prefetch distance in warp-iterations
#define PF_ROWS (PF_ITERS * WARPS_PER_BLOCK)

// Scratch: per-(b,split) context vector + (M, D). 1 MB total.
__device__ float g_ctx[B_DIM * SPLITS * H_DIM];
__device__ float g_m[B_DIM * SPLITS];
__device__ float g_d[B_DIM * SPLITS];
__device__ int   g_cnt[B_DIM];          // zero-initialized; reset by last CTA each run

__device__ __forceinline__ void prefetch_l2(const void* p) {
    asm volatile("prefetch.global.L2 [%0];" :: "l"(p));
}

// ---------------------------------------------------------------------------
// R13 structure, prefetch distance 1 iteration (following the measured
// distance curve: 2 -> 39.4, 3 -> 42.3, 4 -> 43.8 us).
// grid: (SPLITS, B) = 256 CTAs, block 256 (8 warps), occ 2.
// ---------------------------------------------------------------------------
__global__ __launch_bounds__(256, 2)
void attn_fused(const float* __restrict__ enc,   // [L, B, H]
                const float* __restrict__ dec,   // [1, B, H]
                float* __restrict__ out)         // [B, H]
{
    const int s    = blockIdx.x;
    const int b    = blockIdx.y;
    const int warp = threadIdx.x >> 5;
    const int lane = threadIdx.x & 31;

    __shared__ float s_acc[WARPS_PER_BLOCK][H_DIM];   // 32 KB
    __shared__ float s_m[WARPS_PER_BLOCK];
    __shared__ float s_d[WARPS_PER_BLOCK];
    __shared__ float s_scale[WARPS_PER_BLOCK];
    __shared__ int   s_is_last;

    // Decoder slice in registers: h = k*128 + lane*4
    const float4* dec4 = reinterpret_cast<const float4*>(dec + (size_t)b * H_DIM);
    float4 dv[HV];
#pragma unroll
    for (int k = 0; k < HV; k++) dv[k] = dec4[k * 32 + lane];

    float4 acc[HV];
#pragma unroll
    for (int k = 0; k < HV; k++) acc[k] = make_float4(0.f, 0.f, 0.f, 0.f);
    float m = -CUDART_INF_F;
    float d = 0.f;

    const int l0 = s * ROWS_PER_SPLIT + warp;
    const int l1 = (s + 1) * ROWS_PER_SPLIT;

    // Warm the prefetch pipeline: the first PF_ITERS iterations' rows.
#pragma unroll
    for (int i = 0; i < PF_ITERS; i++) {
        const int lw = min(l0 + i * WARPS_PER_BLOCK, l1 - 1);
        const char* pw = reinterpret_cast<const char*>(
            enc + ((size_t)lw * B_DIM + b) * H_DIM);
        prefetch_l2(pw + lane * 128);
    }

    for (int l = l0; l < l1; l += WARPS_PER_BLOCK) {
        // ---- prefetch the row PF_ITERS iterations ahead (1 inst, 0 regs) ----
        {
            const int lp = min(l + PF_ROWS, l1 - 1);   // clamp: stay in-bounds
            const char* pp = reinterpret_cast<const char*>(
                enc + ((size_t)lp * B_DIM + b) * H_DIM);
            prefetch_l2(pp + lane * 128);              // 32 lanes cover 4 KB row
        }

        const float4* e4 =
            reinterpret_cast<const float4*>(enc + ((size_t)l * B_DIM + b) * H_DIM);
        float4 ev[HV];
#pragma unroll
        for (int k = 0; k < HV; k++) ev[k] = __ldcs(&e4[k * 32 + lane]);  // L2-hot

        // dot(e, dec): per-thread partial, warp butterfly reduce
        float sc = 0.f;
#pragma unroll
        for (int k = 0; k < HV; k++) {
            sc = fmaf(ev[k].x, dv[k].x, sc);
            sc = fmaf(ev[k].y, dv[k].y, sc);
            sc = fmaf(ev[k].z, dv[k].z, sc);
            sc = fmaf(ev[k].w, dv[k].w, sc);
        }
#pragma unroll
        for (int off = 16; off > 0; off >>= 1)
            sc += __shfl_xor_sync(0xffffffffu, sc, off);

        // branch-free online softmax update (R3 form)
        float nm    = fmaxf(m, sc);
        float alpha = __expf(m - nm);     // 0 on first iter (m = -inf)
        float w     = __expf(sc - nm);
        d = d * alpha + w;
        m = nm;
#pragma unroll
        for (int k = 0; k < HV; k++) {
            acc[k].x = fmaf(w, ev[k].x, acc[k].x * alpha);
            acc[k].y = fmaf(w, ev[k].y, acc[k].y * alpha);
            acc[k].z = fmaf(w, ev[k].z, acc[k].z * alpha);
            acc[k].w = fmaf(w, ev[k].w, acc[k].w * alpha);
        }
    }

    // ---- in-block flash combine of the 8 warp partials ----
#pragma unroll
    for (int k = 0; k < HV; k++)
        *reinterpret_cast<float4*>(&s_acc[warp][k * 128 + lane * 4]) = acc[k];
    if (lane == 0) { s_m[warp] = m; s_d[warp] = d; }
    __syncthreads();

    if (threadIdx.x == 0) {
        float M = -CUDART_INF_F;
#pragma unroll
        for (int w = 0; w < WARPS_PER_BLOCK; w++) M = fmaxf(M, s_m[w]);
        float D = 0.f;
#pragma unroll
        for (int w = 0; w < WARPS_PER_BLOCK; w++) {
            float sc = __expf(s_m[w] - M);
            s_scale[w] = sc;
            D += s_d[w] * sc;
        }
        const int pid = b * SPLITS + s;
        g_m[pid] = M;
        g_d[pid] = D;
    }
    __syncthreads();

    // Each thread reduces 4 h-positions across the 8 warp slots (float4).
    {
        const int h = threadIdx.x * 4;
        float4 sum = make_float4(0.f, 0.f, 0.f, 0.f);
#pragma unroll
        for (int w = 0; w < WARPS_PER_BLOCK; w++) {
            float sc = s_scale[w];
            float4 v = *reinterpret_cast<const float4*>(&s_acc[w][h]);
            sum.x = fmaf(sc, v.x, sum.x);
            sum.y = fmaf(sc, v.y, sum.y);
            sum.z = fmaf(sc, v.z, sum.z);
            sum.w = fmaf(sc, v.w, sum.w);
        }
        const int pid = b * SPLITS + s;
        *reinterpret_cast<float4*>(&g_ctx[(size_t)pid * H_DIM + h]) = sum;
    }

    // ---- last-CTA-per-b cross-split combine ----
    __threadfence();
    if (threadIdx.x == 0)
        s_is_last = (atomicAdd(&g_cnt[b], 1) == SPLITS - 1) ? 1 : 0;
    __syncthreads();
    if (!s_is_last) return;

    __threadfence();   // acquire: order reads of peers' partials after the atomic

    float M = -CUDART_INF_F;
#pragma unroll
    for (int p = 0; p < SPLITS; p++) M = fmaxf(M, g_m[b * SPLITS + p]);
    float D = 0.f;
    float scale[SPLITS];
#pragma unroll
    for (int p = 0; p < SPLITS; p++) {
        scale[p] = __expf(g_m[b * SPLITS + p] - M);
        D += g_d[b * SPLITS + p] * scale[p];
    }
    const float invD = 1.f / D;

    {
        const int h = threadIdx.x * 4;
        float4 sum = make_float4(0.f, 0.f, 0.f, 0.f);
#pragma unroll
        for (int p = 0; p < SPLITS; p++) {
            const float sc = scale[p] * invD;
            float4 v = *reinterpret_cast<const float4*>(
                &g_ctx[((size_t)(b * SPLITS + p)) * H_DIM + h]);
            sum.x = fmaf(sc, v.x, sum.x);
            sum.y = fmaf(sc, v.y, sum.y);
            sum.z = fmaf(sc, v.z, sum.z);
            sum.w = fmaf(sc, v.w, sum.w);
        }
        *reinterpret_cast<float4*>(&out[(size_t)b * H_DIM + h]) = sum;
    }

    if (threadIdx.x == 0) g_cnt[b] = 0;   // reset for next graph replay
}

// ---------------------------------------------------------------------------
extern "C" void kernel_launch(void* const* d_in, const int* in_sizes, int n_in,
                              void* d_out, int out_size)
{
    const float* enc = (const float*)d_in[0];   // [1024, 64, 1024]
    const float* dec = (const float*)d_in[1];   // [1, 64, 1024]
    float* out = (float*)d_out;                 // [64, 1024]

    dim3 grid(SPLITS, B_DIM);
    attn_fused<<<grid, 256>>>(enc, dec, out);
}